// round 2
// baseline (speedup 1.0000x reference)
#include <cuda_runtime.h>
#include <math.h>

#define N0 300000
#define N1 150000
#define N2C 50000
#define E0C 2400000
#define E1C 800000

// ---------------- device scratch (allocation-guard-safe) ----------------
__device__ float g_h   [(size_t)N0 * 64];
__device__ float g_agg0[(size_t)N1 * 64];
__device__ float g_h1  [(size_t)N1 * 64];
__device__ float g_agg1[(size_t)N2C * 64];
__device__ int   g_deg0[N1];
__device__ int   g_off0[N1 + 1];
__device__ int   g_cur0[N1];
__device__ int   g_es0 [E0C];
__device__ int   g_deg1[N2C];
__device__ int   g_off1[N2C + 1];
__device__ int   g_cur1[N2C];
__device__ int   g_es1 [E1C];
__device__ int   g_part0[1024];
__device__ int   g_part1[1024];

// ---------------- small helpers ----------------
__device__ __forceinline__ void fma16(float* acc, float a, const float* w) {
#pragma unroll
    for (int j4 = 0; j4 < 4; j4++) {
        float4 ww = *(const float4*)&w[j4 * 4];
        acc[j4 * 4 + 0] += a * ww.x;
        acc[j4 * 4 + 1] += a * ww.y;
        acc[j4 * 4 + 2] += a * ww.z;
        acc[j4 * 4 + 3] += a * ww.w;
    }
}

__device__ __forceinline__ void fma64(float* acc, float a, const float* w) {
#pragma unroll
    for (int j4 = 0; j4 < 16; j4++) {
        float4 ww = *(const float4*)&w[j4 * 4];
        acc[j4 * 4 + 0] += a * ww.x;
        acc[j4 * 4 + 1] += a * ww.y;
        acc[j4 * 4 + 2] += a * ww.z;
        acc[j4 * 4 + 3] += a * ww.w;
    }
}

// 1024-thread block inclusive scan
__device__ __forceinline__ int blockScanInc(int v) {
    __shared__ int ws[32];
    int lane = threadIdx.x & 31;
    int wid  = threadIdx.x >> 5;
#pragma unroll
    for (int o = 1; o < 32; o <<= 1) {
        int t = __shfl_up_sync(0xffffffffu, v, o);
        if (lane >= o) v += t;
    }
    if (lane == 31) ws[wid] = v;
    __syncthreads();
    if (wid == 0) {
        int w = ws[lane];
#pragma unroll
        for (int o = 1; o < 32; o <<= 1) {
            int t = __shfl_up_sync(0xffffffffu, w, o);
            if (lane >= o) w += t;
        }
        ws[lane] = w;
    }
    __syncthreads();
    int add = (wid > 0) ? ws[wid - 1] : 0;
    return v + add;
}

// ---------------- kernels ----------------
__global__ void k_zero(int* deg0, int* deg1, int* off0, int* off1) {
    int i = blockIdx.x * blockDim.x + threadIdx.x;
    if (i < N1)  deg0[i] = 0;
    if (i < N2C) deg1[i] = 0;
    if (i == 0) { off0[N1] = 0; off1[N2C] = 0; }
}

__global__ void k_hist(const int* __restrict__ dst, int E, int* __restrict__ deg) {
    int i = blockIdx.x * blockDim.x + threadIdx.x;
    if (i < E) atomicAdd(&deg[dst[i]], 1);
}

__global__ void k_scan1(const int* __restrict__ deg, int* __restrict__ off,
                        int* __restrict__ part, int n) {
    int i = blockIdx.x * 1024 + threadIdx.x;
    int v = (i < n) ? deg[i] : 0;
    int inc = blockScanInc(v);
    if (i < n) off[i] = inc - v;            // block-local exclusive
    if (threadIdx.x == 1023) part[blockIdx.x] = inc;
}

__global__ void k_scan2(int* __restrict__ part, int nb, int* __restrict__ off, int n) {
    int v = (threadIdx.x < nb) ? part[threadIdx.x] : 0;
    int inc = blockScanInc(v);
    if (threadIdx.x < nb) part[threadIdx.x] = inc - v;  // exclusive block offsets
    if (threadIdx.x == nb - 1) off[n] = inc;            // total = E
}

__global__ void k_scan3(int* __restrict__ off, int* __restrict__ cur,
                        const int* __restrict__ part, int n) {
    int i = blockIdx.x * 1024 + threadIdx.x;
    if (i < n) {
        int o = off[i] + part[blockIdx.x];
        off[i] = o;
        cur[i] = o;
    }
}

__global__ void k_scatter(const int* __restrict__ src, const int* __restrict__ dst,
                          int* __restrict__ cur, int* __restrict__ es, int E) {
    int i = blockIdx.x * blockDim.x + threadIdx.x;
    if (i < E) {
        int d = dst[i];
        int p = atomicAdd(&cur[d], 1);
        es[p] = src[i];
    }
}

// warp-per-node mean aggregation; lane l accumulates feats l and l+32
__global__ void k_agg(const float* __restrict__ hsrc, const int* __restrict__ off,
                      const int* __restrict__ es, float* __restrict__ agg, int n) {
    int node = (blockIdx.x * blockDim.x + threadIdx.x) >> 5;
    if (node >= n) return;
    int lane = threadIdx.x & 31;
    int s = off[node];
    int e = off[node + 1];
    float a0 = 0.f, a1 = 0.f;
    int i = s;
    for (; i + 1 < e; i += 2) {
        int s0 = es[i];
        int s1 = es[i + 1];
        const float* r0 = hsrc + (size_t)s0 * 64;
        const float* r1 = hsrc + (size_t)s1 * 64;
        float v00 = r0[lane], v01 = r0[lane + 32];
        float v10 = r1[lane], v11 = r1[lane + 32];
        a0 += v00 + v10;
        a1 += v01 + v11;
    }
    if (i < e) {
        const float* r0 = hsrc + (size_t)es[i] * 64;
        a0 += r0[lane];
        a1 += r0[lane + 32];
    }
    float inv = 1.f / fmaxf((float)(e - s), 1.f);
    agg[(size_t)node * 64 + lane]      = a0 * inv;
    agg[(size_t)node * 64 + lane + 32] = a1 * inv;
}

// e = relu(h_embd @ We1 + be1); e /= max(||e||,1e-12); e = e @ We2 + be2 -> h[:,56:64]
// 128 threads, 256 rows/block (thread t handles rows t and t+128), K chunked by 32
__global__ void k_embed(const float* __restrict__ hemb,
                        const float* __restrict__ We1, const float* __restrict__ be1,
                        const float* __restrict__ We2, const float* __restrict__ be2,
                        float* __restrict__ h) {
    __shared__ __align__(16) float sA[256 * 33];
    __shared__ __align__(16) float sW[512];
    __shared__ __align__(16) float sW2[128];
    __shared__ float sb1[16];
    __shared__ float sb2[8];
    int tid  = threadIdx.x;
    int row0 = blockIdx.x * 256;
    if (tid < 128) sW2[tid] = We2[tid];
    if (tid < 16)  sb1[tid] = be1[tid];
    if (tid < 8)   sb2[tid] = be2[tid];

    float acc[2][16];
#pragma unroll
    for (int q = 0; q < 2; q++)
#pragma unroll
        for (int j = 0; j < 16; j++) acc[q][j] = 0.f;

    for (int kc = 0; kc < 12; kc++) {
        // stage A tile: 256 rows x 32 cols (pitch 33)
#pragma unroll
        for (int u = 0; u < 16; u++) {
            int idx = tid + u * 128;
            int r = idx >> 3, c4 = idx & 7;
            int row = row0 + r;
            float4 v = make_float4(0.f, 0.f, 0.f, 0.f);
            if (row < N0)
                v = *(const float4*)(hemb + (size_t)row * 384 + kc * 32 + c4 * 4);
            float* p = &sA[r * 33 + c4 * 4];
            p[0] = v.x; p[1] = v.y; p[2] = v.z; p[3] = v.w;
        }
        ((float4*)sW)[tid] = ((const float4*)(We1 + kc * 512))[tid];
        __syncthreads();
#pragma unroll 4
        for (int k = 0; k < 32; k++) {
            const float* wr = &sW[k * 16];
#pragma unroll
            for (int q = 0; q < 2; q++) {
                float a = sA[(tid + q * 128) * 33 + k];
                fma16(acc[q], a, wr);
            }
        }
        __syncthreads();
    }

#pragma unroll
    for (int q = 0; q < 2; q++) {
        int row = row0 + tid + q * 128;
        if (row >= N0) continue;
        float e[16];
        float ss = 0.f;
#pragma unroll
        for (int j = 0; j < 16; j++) {
            float v = acc[q][j] + sb1[j];
            v = v > 0.f ? v : 0.f;
            e[j] = v;
            ss += v * v;
        }
        float sc = 1.f / fmaxf(sqrtf(ss), 1e-12f);
        float o[8];
#pragma unroll
        for (int j = 0; j < 8; j++) o[j] = 0.f;
#pragma unroll
        for (int k = 0; k < 16; k++) {
            float ek = e[k];
#pragma unroll
            for (int j = 0; j < 8; j++) o[j] += ek * sW2[k * 8 + j];
        }
        float* hp = h + (size_t)row * 64 + 56;
        *(float4*)(hp)     = make_float4(sc * o[0] + sb2[0], sc * o[1] + sb2[1],
                                         sc * o[2] + sb2[2], sc * o[3] + sb2[3]);
        *(float4*)(hp + 4) = make_float4(sc * o[4] + sb2[4], sc * o[5] + sb2[5],
                                         sc * o[6] + sb2[6], sc * o[7] + sb2[7]);
    }
}

// typed projection -> h[:,0:56]; zero-padded per-type weights, no divergence
#define TSTRIDE 904   // 16*56 + 8 (bank-shifted type stride)
__global__ void k_proj(const float* __restrict__ feats, const int* __restrict__ ntypes,
                       const float* __restrict__ Wd, const float* __restrict__ bd,
                       const float* __restrict__ Wi, const float* __restrict__ bi,
                       const float* __restrict__ Wn, const float* __restrict__ bn,
                       float* __restrict__ h) {
    __shared__ __align__(16) float sW[3 * TSTRIDE];
    __shared__ float sB[3 * 57];
    int tid = threadIdx.x;
    for (int i = tid; i < 3 * TSTRIDE; i += blockDim.x) sW[i] = 0.f;
    __syncthreads();
    for (int i = tid; i < 12 * 56; i += blockDim.x) sW[i] = Wd[i];
    for (int i = tid; i < 10 * 56; i += blockDim.x) sW[TSTRIDE + i] = Wi[i];
    for (int i = tid; i < 16 * 56; i += blockDim.x) sW[2 * TSTRIDE + i] = Wn[i];
    for (int i = tid; i < 56; i += blockDim.x) {
        sB[i] = bd[i]; sB[57 + i] = bi[i]; sB[114 + i] = bn[i];
    }
    __syncthreads();

    int node = blockIdx.x * blockDim.x + tid;
    if (node >= N0) return;
    int t = ntypes[node];
    const float* W = &sW[t * TSTRIDE];
    const float* B = &sB[t * 57];
    float f[16];
    {
        const float4* fp = (const float4*)(feats + (size_t)node * 16);
        float4 f0 = fp[0], f1 = fp[1], f2 = fp[2], f3 = fp[3];
        f[0]=f0.x; f[1]=f0.y; f[2]=f0.z; f[3]=f0.w;
        f[4]=f1.x; f[5]=f1.y; f[6]=f1.z; f[7]=f1.w;
        f[8]=f2.x; f[9]=f2.y; f[10]=f2.z; f[11]=f2.w;
        f[12]=f3.x; f[13]=f3.y; f[14]=f3.z; f[15]=f3.w;
    }
    float acc[56];
#pragma unroll
    for (int j = 0; j < 56; j++) acc[j] = B[j];
#pragma unroll
    for (int k = 0; k < 16; k++) {
        float fk = f[k];
        const float* wr = &W[k * 56];
#pragma unroll
        for (int j4 = 0; j4 < 14; j4++) {
            float4 w = *(const float4*)&wr[j4 * 4];
            acc[j4 * 4 + 0] += fk * w.x;
            acc[j4 * 4 + 1] += fk * w.y;
            acc[j4 * 4 + 2] += fk * w.z;
            acc[j4 * 4 + 3] += fk * w.w;
        }
    }
    float* out = h + (size_t)node * 64;
#pragma unroll
    for (int j4 = 0; j4 < 14; j4++)
        *(float4*)&out[j4 * 4] = make_float4(acc[j4 * 4], acc[j4 * 4 + 1],
                                             acc[j4 * 4 + 2], acc[j4 * 4 + 3]);
}

// h1 = relu(h[:n] @ Ws + agg @ Wn + bs)  (64+64 -> 64), thread-per-row, 128 rows/block
__global__ void k_h1(const float* __restrict__ hin, const float* __restrict__ agg,
                     const float* __restrict__ Ws, const float* __restrict__ Wn,
                     const float* __restrict__ bs, float* __restrict__ hout, int nrows) {
    extern __shared__ float sm[];
    float* sT = sm;               // 128*65
    float* sW = sm + 128 * 65;    // 64*64
    int tid  = threadIdx.x;
    int row0 = blockIdx.x * 128;
    int row  = row0 + tid;

    float acc[64];
#pragma unroll
    for (int j = 0; j < 64; j++) acc[j] = bs[j];

    // ---- phase 1: self term ----
#pragma unroll
    for (int u = 0; u < 16; u++) {
        int idx = tid + u * 128;
        int r = idx >> 4, c4 = idx & 15;
        int rr = row0 + r;
        float4 v = (rr < nrows) ? *(const float4*)(hin + (size_t)rr * 64 + c4 * 4)
                                : make_float4(0.f, 0.f, 0.f, 0.f);
        float* p = &sT[r * 65 + c4 * 4];
        p[0] = v.x; p[1] = v.y; p[2] = v.z; p[3] = v.w;
    }
#pragma unroll
    for (int u = 0; u < 8; u++)
        ((float4*)sW)[tid + u * 128] = ((const float4*)Ws)[tid + u * 128];
    __syncthreads();
#pragma unroll 4
    for (int k = 0; k < 64; k++) {
        float a = sT[tid * 65 + k];
        fma64(acc, a, &sW[k * 64]);
    }
    __syncthreads();

    // ---- phase 2: neighbor term ----
#pragma unroll
    for (int u = 0; u < 16; u++) {
        int idx = tid + u * 128;
        int r = idx >> 4, c4 = idx & 15;
        int rr = row0 + r;
        float4 v = (rr < nrows) ? *(const float4*)(agg + (size_t)rr * 64 + c4 * 4)
                                : make_float4(0.f, 0.f, 0.f, 0.f);
        float* p = &sT[r * 65 + c4 * 4];
        p[0] = v.x; p[1] = v.y; p[2] = v.z; p[3] = v.w;
    }
#pragma unroll
    for (int u = 0; u < 8; u++)
        ((float4*)sW)[tid + u * 128] = ((const float4*)Wn)[tid + u * 128];
    __syncthreads();
#pragma unroll 4
    for (int k = 0; k < 64; k++) {
        float a = sT[tid * 65 + k];
        fma64(acc, a, &sW[k * 64]);
    }

    if (row < nrows) {
        float* out = hout + (size_t)row * 64;
#pragma unroll
        for (int j4 = 0; j4 < 16; j4++) {
            float4 v;
            v.x = fmaxf(acc[j4 * 4 + 0], 0.f);
            v.y = fmaxf(acc[j4 * 4 + 1], 0.f);
            v.z = fmaxf(acc[j4 * 4 + 2], 0.f);
            v.w = fmaxf(acc[j4 * 4 + 3], 0.f);
            *(float4*)&out[j4 * 4] = v;
        }
    }
}

// h2 = h1[:n2]@Ws1 + agg1@Wn1 + bs1 ; net_h=[h2,feats16] ; 3-layer MLP -> logits
__global__ void k_h2cls(const float* __restrict__ h1, const float* __restrict__ agg1,
                        const float* __restrict__ feats,
                        const float* __restrict__ Ws1, const float* __restrict__ Wn1,
                        const float* __restrict__ bs1,
                        const float* __restrict__ Wc1, const float* __restrict__ bc1,
                        const float* __restrict__ Wc2, const float* __restrict__ bc2,
                        const float* __restrict__ Wc3, const float* __restrict__ bc3,
                        float* __restrict__ logits, float* __restrict__ h2out) {
    extern __shared__ float sm[];
    float* sT = sm;                 // 128*65
    float* sU = sm + 8320;          // 128*65
    float* sW = sm + 16640;         // up to 80*64
    float* sF = sm + 21760;         // 128*17
    float* sB = sm + 23936;         // 256 biases
    int tid  = threadIdx.x;
    int row0 = blockIdx.x * 128;
    int row  = row0 + tid;
    bool valid = row < N2C;

    // stage h1 tile, agg1 tile, feats tile, Ws1, biases
#pragma unroll
    for (int u = 0; u < 16; u++) {
        int idx = tid + u * 128;
        int r = idx >> 4, c4 = idx & 15;
        int rr = row0 + r;
        float4 v = *(const float4*)(h1 + (size_t)rr * 64 + c4 * 4);  // rr < N1 always
        float* p = &sT[r * 65 + c4 * 4];
        p[0] = v.x; p[1] = v.y; p[2] = v.z; p[3] = v.w;
        float4 va = (rr < N2C) ? *(const float4*)(agg1 + (size_t)rr * 64 + c4 * 4)
                               : make_float4(0.f, 0.f, 0.f, 0.f);
        float* pu = &sU[r * 65 + c4 * 4];
        pu[0] = va.x; pu[1] = va.y; pu[2] = va.z; pu[3] = va.w;
    }
#pragma unroll
    for (int u = 0; u < 4; u++) {
        int idx = tid + u * 128;
        int r = idx >> 2, c4 = idx & 3;
        int rr = row0 + r;
        float4 v = *(const float4*)(feats + (size_t)rr * 16 + c4 * 4);  // rr < N0 always
        float* p = &sF[r * 17 + c4 * 4];
        p[0] = v.x; p[1] = v.y; p[2] = v.z; p[3] = v.w;
    }
#pragma unroll
    for (int u = 0; u < 8; u++)
        ((float4*)sW)[tid + u * 128] = ((const float4*)Ws1)[tid + u * 128];
    if (tid < 64) {
        sB[tid] = bs1[tid];
        sB[64 + tid] = bc1[tid];
        sB[128 + tid] = bc2[tid];
    }
    if (tid < 8) sB[192 + tid] = bc3[tid];
    __syncthreads();

    float acc[64];
#pragma unroll
    for (int j = 0; j < 64; j++) acc[j] = sB[j];
#pragma unroll 4
    for (int k = 0; k < 64; k++) fma64(acc, sT[tid * 65 + k], &sW[k * 64]);
    __syncthreads();
#pragma unroll
    for (int u = 0; u < 8; u++)
        ((float4*)sW)[tid + u * 128] = ((const float4*)Wn1)[tid + u * 128];
    __syncthreads();
#pragma unroll 4
    for (int k = 0; k < 64; k++) fma64(acc, sU[tid * 65 + k], &sW[k * 64]);

    // acc = h2 (no relu): write out
    if (valid) {
        float* out = h2out + (size_t)row * 64;
#pragma unroll
        for (int j4 = 0; j4 < 16; j4++)
            *(float4*)&out[j4 * 4] = make_float4(acc[j4 * 4], acc[j4 * 4 + 1],
                                                 acc[j4 * 4 + 2], acc[j4 * 4 + 3]);
    }
    __syncthreads();
    // park h2 in sU, stage Wc1 (80x64)
#pragma unroll
    for (int k = 0; k < 64; k++) sU[tid * 65 + k] = acc[k];
#pragma unroll
    for (int u = 0; u < 10; u++)
        ((float4*)sW)[tid + u * 128] = ((const float4*)Wc1)[tid + u * 128];
    __syncthreads();

    float x[64];
#pragma unroll
    for (int j = 0; j < 64; j++) x[j] = sB[64 + j];
#pragma unroll 4
    for (int k = 0; k < 64; k++) fma64(x, sU[tid * 65 + k], &sW[k * 64]);
#pragma unroll
    for (int k = 0; k < 16; k++) fma64(x, sF[tid * 17 + k], &sW[(64 + k) * 64]);
#pragma unroll
    for (int j = 0; j < 64; j++) x[j] = fmaxf(x[j], 0.f);
    __syncthreads();
    // park x in sT, stage Wc2
#pragma unroll
    for (int k = 0; k < 64; k++) sT[tid * 65 + k] = x[k];
#pragma unroll
    for (int u = 0; u < 8; u++)
        ((float4*)sW)[tid + u * 128] = ((const float4*)Wc2)[tid + u * 128];
    __syncthreads();

#pragma unroll
    for (int j = 0; j < 64; j++) acc[j] = sB[128 + j];
#pragma unroll 4
    for (int k = 0; k < 64; k++) fma64(acc, sT[tid * 65 + k], &sW[k * 64]);
#pragma unroll
    for (int j = 0; j < 64; j++) acc[j] = fmaxf(acc[j], 0.f);
    __syncthreads();
    // park x2 in sU, stage Wc3 (64x8)
#pragma unroll
    for (int k = 0; k < 64; k++) sU[tid * 65 + k] = acc[k];
    if (tid < 128) ((float4*)sW)[tid] = ((const float4*)Wc3)[tid];
    __syncthreads();

    float lg[8];
#pragma unroll
    for (int j = 0; j < 8; j++) lg[j] = sB[192 + j];
#pragma unroll 4
    for (int k = 0; k < 64; k++) {
        float a = sU[tid * 65 + k];
        float4 w0 = *(const float4*)&sW[k * 8];
        float4 w1 = *(const float4*)&sW[k * 8 + 4];
        lg[0] += a * w0.x; lg[1] += a * w0.y; lg[2] += a * w0.z; lg[3] += a * w0.w;
        lg[4] += a * w1.x; lg[5] += a * w1.y; lg[6] += a * w1.z; lg[7] += a * w1.w;
    }
    if (valid) {
        float* lp = logits + (size_t)row * 8;
        *(float4*)(lp)     = make_float4(lg[0], lg[1], lg[2], lg[3]);
        *(float4*)(lp + 4) = make_float4(lg[4], lg[5], lg[6], lg[7]);
    }
}

// ---------------- host launch ----------------
extern "C" void kernel_launch(void* const* d_in, const int* in_sizes, int n_in,
                              void* d_out, int out_size) {
    const float* feats  = (const float*)d_in[0];
    const int*   ntypes = (const int*)d_in[1];
    const float* hemb   = (const float*)d_in[2];
    const int*   src0   = (const int*)d_in[3];
    const int*   dst0   = (const int*)d_in[4];
    const int*   src1   = (const int*)d_in[5];
    const int*   dst1   = (const int*)d_in[6];
    int wi = (n_in >= 31) ? 9 : 7;   // skip scalar n1, n2 if present
    const float* Wd  = (const float*)d_in[wi + 0];
    const float* bd  = (const float*)d_in[wi + 1];
    const float* Wi_ = (const float*)d_in[wi + 2];
    const float* bi  = (const float*)d_in[wi + 3];
    const float* Wn  = (const float*)d_in[wi + 4];
    const float* bn  = (const float*)d_in[wi + 5];
    const float* We1 = (const float*)d_in[wi + 6];
    const float* be1 = (const float*)d_in[wi + 7];
    const float* We2 = (const float*)d_in[wi + 8];
    const float* be2 = (const float*)d_in[wi + 9];
    const float* Ws0 = (const float*)d_in[wi + 10];
    const float* Wn0 = (const float*)d_in[wi + 11];
    const float* bs0 = (const float*)d_in[wi + 12];
    const float* Ws1 = (const float*)d_in[wi + 13];
    const float* Wn1 = (const float*)d_in[wi + 14];
    const float* bs1 = (const float*)d_in[wi + 15];
    const float* Wc1 = (const float*)d_in[wi + 16];
    const float* bc1 = (const float*)d_in[wi + 17];
    const float* Wc2 = (const float*)d_in[wi + 18];
    const float* bc2 = (const float*)d_in[wi + 19];
    const float* Wc3 = (const float*)d_in[wi + 20];
    const float* bc3 = (const float*)d_in[wi + 21];

    float* logits = (float*)d_out;
    float* h2out  = (float*)d_out + (size_t)N2C * 8;

    float *p_h, *p_agg0, *p_h1, *p_agg1;
    int *p_deg0, *p_off0, *p_cur0, *p_es0;
    int *p_deg1, *p_off1, *p_cur1, *p_es1;
    int *p_part0, *p_part1;
    cudaGetSymbolAddress((void**)&p_h,    g_h);
    cudaGetSymbolAddress((void**)&p_agg0, g_agg0);
    cudaGetSymbolAddress((void**)&p_h1,   g_h1);
    cudaGetSymbolAddress((void**)&p_agg1, g_agg1);
    cudaGetSymbolAddress((void**)&p_deg0, g_deg0);
    cudaGetSymbolAddress((void**)&p_off0, g_off0);
    cudaGetSymbolAddress((void**)&p_cur0, g_cur0);
    cudaGetSymbolAddress((void**)&p_es0,  g_es0);
    cudaGetSymbolAddress((void**)&p_deg1, g_deg1);
    cudaGetSymbolAddress((void**)&p_off1, g_off1);
    cudaGetSymbolAddress((void**)&p_cur1, g_cur1);
    cudaGetSymbolAddress((void**)&p_es1,  g_es1);
    cudaGetSymbolAddress((void**)&p_part0, g_part0);
    cudaGetSymbolAddress((void**)&p_part1, g_part1);

    const int SMEM_H1 = (128 * 65 + 64 * 64) * 4;              // 49664
    const int SMEM_H2 = (8320 + 8320 + 5120 + 2176 + 256) * 4; // 96768
    cudaFuncSetAttribute(k_h1,    cudaFuncAttributeMaxDynamicSharedMemorySize, SMEM_H1);
    cudaFuncSetAttribute(k_h2cls, cudaFuncAttributeMaxDynamicSharedMemorySize, SMEM_H2);

    int nb0 = (N1 + 1023) / 1024;   // 147
    int nb1 = (N2C + 1023) / 1024;  // 49

    k_zero<<<(N1 + 255) / 256, 256>>>(p_deg0, p_deg1, p_off0, p_off1);
    k_embed<<<(N0 + 255) / 256, 128>>>(hemb, We1, be1, We2, be2, p_h);
    k_proj<<<(N0 + 127) / 128, 128>>>(feats, ntypes, Wd, bd, Wi_, bi, Wn, bn, p_h);

    // ---- layer 0 CSR + aggregate ----
    k_hist<<<(E0C + 255) / 256, 256>>>(dst0, E0C, p_deg0);
    k_scan1<<<nb0, 1024>>>(p_deg0, p_off0, p_part0, N1);
    k_scan2<<<1, 1024>>>(p_part0, nb0, p_off0, N1);
    k_scan3<<<nb0, 1024>>>(p_off0, p_cur0, p_part0, N1);
    k_scatter<<<(E0C + 255) / 256, 256>>>(src0, dst0, p_cur0, p_es0, E0C);
    k_agg<<<(N1 + 7) / 8, 256>>>(p_h, p_off0, p_es0, p_agg0, N1);

    k_h1<<<(N1 + 127) / 128, 128, SMEM_H1>>>(p_h, p_agg0, Ws0, Wn0, bs0, p_h1, N1);

    // ---- layer 1 CSR + aggregate ----
    k_hist<<<(E1C + 255) / 256, 256>>>(dst1, E1C, p_deg1);
    k_scan1<<<nb1, 1024>>>(p_deg1, p_off1, p_part1, N2C);
    k_scan2<<<1, 1024>>>(p_part1, nb1, p_off1, N2C);
    k_scan3<<<nb1, 1024>>>(p_off1, p_cur1, p_part1, N2C);
    k_scatter<<<(E1C + 255) / 256, 256>>>(src1, dst1, p_cur1, p_es1, E1C);
    k_agg<<<(N2C + 7) / 8, 256>>>(p_h1, p_off1, p_es1, p_agg1, N2C);

    k_h2cls<<<(N2C + 127) / 128, 128, SMEM_H2>>>(p_h1, p_agg1, feats,
                                                 Ws1, Wn1, bs1,
                                                 Wc1, bc1, Wc2, bc2, Wc3, bc3,
                                                 logits, h2out);
}

// round 3
// speedup vs baseline: 1.0210x; 1.0210x over previous
#include <cuda_runtime.h>
#include <math.h>

#define N0 300000
#define N1 150000
#define N2C 50000
#define E0C 2400000
#define E1C 800000

// ---------------- device scratch (allocation-guard-safe) ----------------
__device__ float g_h   [(size_t)N0 * 64];
__device__ float g_agg0[(size_t)N1 * 64];
__device__ float g_h1  [(size_t)N1 * 64];
__device__ float g_agg1[(size_t)N2C * 64];
__device__ int   g_deg0[N1];
__device__ int   g_off0[N1 + 1];
__device__ int   g_cur0[N1];
__device__ int   g_es0 [E0C];
__device__ int   g_deg1[N2C];
__device__ int   g_off1[N2C + 1];
__device__ int   g_cur1[N2C];
__device__ int   g_es1 [E1C];
__device__ int   g_part0[1024];
__device__ int   g_part1[1024];

// ---------------- packed f32x2 helpers ----------------
__device__ __forceinline__ unsigned long long pack2(float a, float b) {
    unsigned long long r;
    asm("mov.b64 %0, {%1,%2};" : "=l"(r) : "f"(a), "f"(b));
    return r;
}
__device__ __forceinline__ float2 unpack2(unsigned long long v) {
    float2 f;
    asm("mov.b64 {%0,%1}, %2;" : "=f"(f.x), "=f"(f.y) : "l"(v));
    return f;
}
__device__ __forceinline__ unsigned long long fma2p(unsigned long long a,
                                                    unsigned long long b,
                                                    unsigned long long c) {
    unsigned long long d;
    asm("fma.rn.f32x2 %0, %1, %2, %3;" : "=l"(d) : "l"(a), "l"(b), "l"(c));
    return d;
}

// acc2: 32 packed pairs (64 floats); w: 16B-aligned row of 64 floats in smem
__device__ __forceinline__ void fma64p(unsigned long long* acc2, unsigned long long aa,
                                       const float* w) {
#pragma unroll
    for (int j = 0; j < 16; j++) {
        ulonglong2 ww = *(const ulonglong2*)(w + j * 4);
        acc2[2 * j]     = fma2p(aa, ww.x, acc2[2 * j]);
        acc2[2 * j + 1] = fma2p(aa, ww.y, acc2[2 * j + 1]);
    }
}

// 1024-thread block inclusive scan
__device__ __forceinline__ int blockScanInc(int v) {
    __shared__ int ws[32];
    int lane = threadIdx.x & 31;
    int wid  = threadIdx.x >> 5;
#pragma unroll
    for (int o = 1; o < 32; o <<= 1) {
        int t = __shfl_up_sync(0xffffffffu, v, o);
        if (lane >= o) v += t;
    }
    if (lane == 31) ws[wid] = v;
    __syncthreads();
    if (wid == 0) {
        int w = ws[lane];
#pragma unroll
        for (int o = 1; o < 32; o <<= 1) {
            int t = __shfl_up_sync(0xffffffffu, w, o);
            if (lane >= o) w += t;
        }
        ws[lane] = w;
    }
    __syncthreads();
    int add = (wid > 0) ? ws[wid - 1] : 0;
    return v + add;
}

// ---------------- CSR-build kernels (both layers fused) ----------------
__global__ void k_zero(int* deg0, int* deg1) {
    int i = blockIdx.x * blockDim.x + threadIdx.x;
    if (i < N1)  deg0[i] = 0;
    if (i < N2C) deg1[i] = 0;
}

__global__ void k_hist2(const int* __restrict__ dst0, const int* __restrict__ dst1,
                        int* __restrict__ deg0, int* __restrict__ deg1) {
    int i = blockIdx.x * blockDim.x + threadIdx.x;
    if (i < E0C) atomicAdd(&deg0[dst0[i]], 1);
    else if (i < E0C + E1C) atomicAdd(&deg1[dst1[i - E0C]], 1);
}

__global__ void k_scan1(const int* __restrict__ deg0, int* __restrict__ off0,
                        int* __restrict__ part0, int nb0,
                        const int* __restrict__ deg1, int* __restrict__ off1,
                        int* __restrict__ part1) {
    const int* deg; int* off; int* part; int n; int b;
    if ((int)blockIdx.x < nb0) { deg = deg0; off = off0; part = part0; n = N1;  b = blockIdx.x; }
    else                       { deg = deg1; off = off1; part = part1; n = N2C; b = blockIdx.x - nb0; }
    int i = b * 1024 + threadIdx.x;
    int v = (i < n) ? deg[i] : 0;
    int inc = blockScanInc(v);
    if (i < n) off[i] = inc - v;
    if (threadIdx.x == 1023) part[b] = inc;
}

__global__ void k_scan2(int* __restrict__ part0, int nb0, int* __restrict__ off0,
                        int* __restrict__ part1, int nb1, int* __restrict__ off1) {
    {
        int v = ((int)threadIdx.x < nb0) ? part0[threadIdx.x] : 0;
        int inc = blockScanInc(v);
        if ((int)threadIdx.x < nb0) part0[threadIdx.x] = inc - v;
        if ((int)threadIdx.x == nb0 - 1) off0[N1] = inc;
    }
    __syncthreads();
    {
        int v = ((int)threadIdx.x < nb1) ? part1[threadIdx.x] : 0;
        int inc = blockScanInc(v);
        if ((int)threadIdx.x < nb1) part1[threadIdx.x] = inc - v;
        if ((int)threadIdx.x == nb1 - 1) off1[N2C] = inc;
    }
}

__global__ void k_scan3(int* __restrict__ off0, int* __restrict__ cur0,
                        const int* __restrict__ part0, int nb0,
                        int* __restrict__ off1, int* __restrict__ cur1,
                        const int* __restrict__ part1) {
    int* off; int* cur; const int* part; int n; int b;
    if ((int)blockIdx.x < nb0) { off = off0; cur = cur0; part = part0; n = N1;  b = blockIdx.x; }
    else                       { off = off1; cur = cur1; part = part1; n = N2C; b = blockIdx.x - nb0; }
    int i = b * 1024 + threadIdx.x;
    if (i < n) {
        int o = off[i] + part[b];
        off[i] = o;
        cur[i] = o;
    }
}

__global__ void k_scatter2(const int* __restrict__ src0, const int* __restrict__ dst0,
                           int* __restrict__ cur0, int* __restrict__ es0,
                           const int* __restrict__ src1, const int* __restrict__ dst1,
                           int* __restrict__ cur1, int* __restrict__ es1) {
    int i = blockIdx.x * blockDim.x + threadIdx.x;
    if (i < E0C) {
        int p = atomicAdd(&cur0[dst0[i]], 1);
        es0[p] = src0[i];
    } else if (i < E0C + E1C) {
        int j = i - E0C;
        int p = atomicAdd(&cur1[dst1[j]], 1);
        es1[p] = src1[j];
    }
}

// warp-per-node mean aggregation; lane l accumulates feats l and l+32
__global__ void k_agg(const float* __restrict__ hsrc, const int* __restrict__ off,
                      const int* __restrict__ es, float* __restrict__ agg, int n) {
    int node = (blockIdx.x * blockDim.x + threadIdx.x) >> 5;
    if (node >= n) return;
    int lane = threadIdx.x & 31;
    int s = off[node];
    int e = off[node + 1];
    float a0 = 0.f, a1 = 0.f;
    int i = s;
    for (; i + 1 < e; i += 2) {
        const float* r0 = hsrc + (size_t)es[i] * 64;
        const float* r1 = hsrc + (size_t)es[i + 1] * 64;
        float v00 = r0[lane], v01 = r0[lane + 32];
        float v10 = r1[lane], v11 = r1[lane + 32];
        a0 += v00 + v10;
        a1 += v01 + v11;
    }
    if (i < e) {
        const float* r0 = hsrc + (size_t)es[i] * 64;
        a0 += r0[lane];
        a1 += r0[lane + 32];
    }
    float inv = 1.f / fmaxf((float)(e - s), 1.f);
    agg[(size_t)node * 64 + lane]      = a0 * inv;
    agg[(size_t)node * 64 + lane + 32] = a1 * inv;
}

// ---------------- embedding path: relu(h_embd@We1+be1), l2-norm, @We2+be2 ----------------
// 256 threads, 256 rows/block, 1 row/thread; K chunked by 32; packed f32x2 FMA
__global__ void k_embed(const float* __restrict__ hemb,
                        const float* __restrict__ We1, const float* __restrict__ be1,
                        const float* __restrict__ We2, const float* __restrict__ be2,
                        float* __restrict__ h) {
    __shared__ __align__(16) float sA[256 * 33];
    __shared__ __align__(16) float sW[512];
    __shared__ __align__(16) float sW2[128];
    __shared__ float sb1[16];
    __shared__ float sb2[8];
    int tid  = threadIdx.x;
    int row0 = blockIdx.x * 256;
    if (tid < 128) sW2[tid] = We2[tid];
    if (tid < 16)  sb1[tid] = be1[tid];
    if (tid < 8)   sb2[tid] = be2[tid];

    unsigned long long acc2[8];
#pragma unroll
    for (int j = 0; j < 8; j++) acc2[j] = 0ull;

    for (int kc = 0; kc < 12; kc++) {
        // stage A tile: 256 rows x 32 cols (pitch 33)
#pragma unroll
        for (int u = 0; u < 8; u++) {
            int idx = tid + u * 256;
            int r = idx >> 3, c4 = idx & 7;
            int row = row0 + r;
            float4 v = make_float4(0.f, 0.f, 0.f, 0.f);
            if (row < N0)
                v = *(const float4*)(hemb + (size_t)row * 384 + kc * 32 + c4 * 4);
            float* p = &sA[r * 33 + c4 * 4];
            p[0] = v.x; p[1] = v.y; p[2] = v.z; p[3] = v.w;
        }
        ((float2*)sW)[tid] = ((const float2*)(We1 + kc * 512))[tid];
        __syncthreads();
#pragma unroll 4
        for (int k = 0; k < 32; k++) {
            float a = sA[tid * 33 + k];
            unsigned long long aa = pack2(a, a);
            const float* wr = &sW[k * 16];
#pragma unroll
            for (int j = 0; j < 4; j++) {
                ulonglong2 ww = *(const ulonglong2*)(wr + j * 4);
                acc2[2 * j]     = fma2p(aa, ww.x, acc2[2 * j]);
                acc2[2 * j + 1] = fma2p(aa, ww.y, acc2[2 * j + 1]);
            }
        }
        __syncthreads();
    }

    int row = row0 + tid;
    if (row < N0) {
        float e[16];
        float ss = 0.f;
#pragma unroll
        for (int j = 0; j < 8; j++) {
            float2 p = unpack2(acc2[j]);
            float v0 = p.x + sb1[2 * j];
            float v1 = p.y + sb1[2 * j + 1];
            v0 = v0 > 0.f ? v0 : 0.f;
            v1 = v1 > 0.f ? v1 : 0.f;
            e[2 * j] = v0; e[2 * j + 1] = v1;
            ss += v0 * v0 + v1 * v1;
        }
        float sc = 1.f / fmaxf(sqrtf(ss), 1e-12f);
        float o[8];
#pragma unroll
        for (int j = 0; j < 8; j++) o[j] = 0.f;
#pragma unroll
        for (int k = 0; k < 16; k++) {
            float ek = e[k];
#pragma unroll
            for (int j = 0; j < 8; j++) o[j] += ek * sW2[k * 8 + j];
        }
        float* hp = h + (size_t)row * 64 + 56;
        *(float4*)(hp)     = make_float4(sc * o[0] + sb2[0], sc * o[1] + sb2[1],
                                         sc * o[2] + sb2[2], sc * o[3] + sb2[3]);
        *(float4*)(hp + 4) = make_float4(sc * o[4] + sb2[4], sc * o[5] + sb2[5],
                                         sc * o[6] + sb2[6], sc * o[7] + sb2[7]);
    }
}

// typed projection -> h[:,0:56]; zero-padded per-type weights, packed FMA
#define TSTRIDE 904   // 16*56 + 8 floats (16B-aligned: 3616 bytes)
__global__ void k_proj(const float* __restrict__ feats, const int* __restrict__ ntypes,
                       const float* __restrict__ Wd, const float* __restrict__ bd,
                       const float* __restrict__ Wi, const float* __restrict__ bi,
                       const float* __restrict__ Wn, const float* __restrict__ bn,
                       float* __restrict__ h) {
    __shared__ __align__(16) float sW[3 * TSTRIDE];
    __shared__ float sB[3 * 57];
    int tid = threadIdx.x;
    for (int i = tid; i < 3 * TSTRIDE; i += blockDim.x) sW[i] = 0.f;
    __syncthreads();
    for (int i = tid; i < 12 * 56; i += blockDim.x) sW[i] = Wd[i];
    for (int i = tid; i < 10 * 56; i += blockDim.x) sW[TSTRIDE + i] = Wi[i];
    for (int i = tid; i < 16 * 56; i += blockDim.x) sW[2 * TSTRIDE + i] = Wn[i];
    for (int i = tid; i < 56; i += blockDim.x) {
        sB[i] = bd[i]; sB[57 + i] = bi[i]; sB[114 + i] = bn[i];
    }
    __syncthreads();

    int node = blockIdx.x * blockDim.x + tid;
    if (node >= N0) return;
    int t = ntypes[node];
    const float* W = &sW[t * TSTRIDE];
    const float* B = &sB[t * 57];
    float f[16];
    {
        const float4* fp = (const float4*)(feats + (size_t)node * 16);
        float4 f0 = fp[0], f1 = fp[1], f2 = fp[2], f3 = fp[3];
        f[0]=f0.x; f[1]=f0.y; f[2]=f0.z; f[3]=f0.w;
        f[4]=f1.x; f[5]=f1.y; f[6]=f1.z; f[7]=f1.w;
        f[8]=f2.x; f[9]=f2.y; f[10]=f2.z; f[11]=f2.w;
        f[12]=f3.x; f[13]=f3.y; f[14]=f3.z; f[15]=f3.w;
    }
    unsigned long long acc2[28];
#pragma unroll
    for (int j = 0; j < 28; j++) acc2[j] = pack2(B[2 * j], B[2 * j + 1]);
#pragma unroll
    for (int k = 0; k < 16; k++) {
        unsigned long long fk = pack2(f[k], f[k]);
        const float* wr = &W[k * 56];
#pragma unroll
        for (int j = 0; j < 14; j++) {
            ulonglong2 ww = *(const ulonglong2*)(wr + j * 4);
            acc2[2 * j]     = fma2p(fk, ww.x, acc2[2 * j]);
            acc2[2 * j + 1] = fma2p(fk, ww.y, acc2[2 * j + 1]);
        }
    }
    float* out = h + (size_t)node * 64;
#pragma unroll
    for (int j4 = 0; j4 < 14; j4++) {
        float2 a = unpack2(acc2[2 * j4]);
        float2 b = unpack2(acc2[2 * j4 + 1]);
        *(float4*)&out[j4 * 4] = make_float4(a.x, a.y, b.x, b.y);
    }
}

// h1 = relu(h[:n] @ Ws + agg @ Wn + bs)  (64+64 -> 64), thread-per-row, packed FMA
__global__ void k_h1(const float* __restrict__ hin, const float* __restrict__ agg,
                     const float* __restrict__ Ws, const float* __restrict__ Wn,
                     const float* __restrict__ bs, float* __restrict__ hout, int nrows) {
    extern __shared__ float sm[];
    float* sT = sm;               // 128*65
    float* sW = sm + 128 * 65;    // 64*64 (16B aligned: 33280 bytes)
    int tid  = threadIdx.x;
    int row0 = blockIdx.x * 128;
    int row  = row0 + tid;

    unsigned long long acc2[32];
#pragma unroll
    for (int j = 0; j < 32; j++) acc2[j] = pack2(bs[2 * j], bs[2 * j + 1]);

    // ---- phase 1: self term ----
#pragma unroll
    for (int u = 0; u < 16; u++) {
        int idx = tid + u * 128;
        int r = idx >> 4, c4 = idx & 15;
        int rr = row0 + r;
        float4 v = (rr < nrows) ? *(const float4*)(hin + (size_t)rr * 64 + c4 * 4)
                                : make_float4(0.f, 0.f, 0.f, 0.f);
        float* p = &sT[r * 65 + c4 * 4];
        p[0] = v.x; p[1] = v.y; p[2] = v.z; p[3] = v.w;
    }
#pragma unroll
    for (int u = 0; u < 8; u++)
        ((float4*)sW)[tid + u * 128] = ((const float4*)Ws)[tid + u * 128];
    __syncthreads();
#pragma unroll 4
    for (int k = 0; k < 64; k++) {
        float a = sT[tid * 65 + k];
        fma64p(acc2, pack2(a, a), &sW[k * 64]);
    }
    __syncthreads();

    // ---- phase 2: neighbor term ----
#pragma unroll
    for (int u = 0; u < 16; u++) {
        int idx = tid + u * 128;
        int r = idx >> 4, c4 = idx & 15;
        int rr = row0 + r;
        float4 v = (rr < nrows) ? *(const float4*)(agg + (size_t)rr * 64 + c4 * 4)
                                : make_float4(0.f, 0.f, 0.f, 0.f);
        float* p = &sT[r * 65 + c4 * 4];
        p[0] = v.x; p[1] = v.y; p[2] = v.z; p[3] = v.w;
    }
#pragma unroll
    for (int u = 0; u < 8; u++)
        ((float4*)sW)[tid + u * 128] = ((const float4*)Wn)[tid + u * 128];
    __syncthreads();
#pragma unroll 4
    for (int k = 0; k < 64; k++) {
        float a = sT[tid * 65 + k];
        fma64p(acc2, pack2(a, a), &sW[k * 64]);
    }

    if (row < nrows) {
        float* out = hout + (size_t)row * 64;
#pragma unroll
        for (int j4 = 0; j4 < 16; j4++) {
            float2 a = unpack2(acc2[2 * j4]);
            float2 b = unpack2(acc2[2 * j4 + 1]);
            *(float4*)&out[j4 * 4] = make_float4(fmaxf(a.x, 0.f), fmaxf(a.y, 0.f),
                                                 fmaxf(b.x, 0.f), fmaxf(b.y, 0.f));
        }
    }
}

// h2 = h1[:n2]@Ws1 + agg1@Wn1 + bs1 ; net_h=[h2,feats16] ; 3-layer MLP -> logits
__global__ void k_h2cls(const float* __restrict__ h1, const float* __restrict__ agg1,
                        const float* __restrict__ feats,
                        const float* __restrict__ Ws1, const float* __restrict__ Wn1,
                        const float* __restrict__ bs1,
                        const float* __restrict__ Wc1, const float* __restrict__ bc1,
                        const float* __restrict__ Wc2, const float* __restrict__ bc2,
                        const float* __restrict__ Wc3, const float* __restrict__ bc3,
                        float* __restrict__ logits, float* __restrict__ h2out) {
    extern __shared__ float sm[];
    float* sT = sm;                 // 128*65
    float* sU = sm + 8320;          // 128*65
    float* sW = sm + 16640;         // up to 80*64 (16B aligned)
    float* sF = sm + 21760;         // 128*17
    float* sB = sm + 23936;         // 256 biases
    int tid  = threadIdx.x;
    int row0 = blockIdx.x * 128;
    int row  = row0 + tid;
    bool valid = row < N2C;

    // stage h1 tile, agg1 tile, feats tile, Ws1, biases
#pragma unroll
    for (int u = 0; u < 16; u++) {
        int idx = tid + u * 128;
        int r = idx >> 4, c4 = idx & 15;
        int rr = row0 + r;
        float4 v = *(const float4*)(h1 + (size_t)rr * 64 + c4 * 4);  // rr < N1 always
        float* p = &sT[r * 65 + c4 * 4];
        p[0] = v.x; p[1] = v.y; p[2] = v.z; p[3] = v.w;
        float4 va = (rr < N2C) ? *(const float4*)(agg1 + (size_t)rr * 64 + c4 * 4)
                               : make_float4(0.f, 0.f, 0.f, 0.f);
        float* pu = &sU[r * 65 + c4 * 4];
        pu[0] = va.x; pu[1] = va.y; pu[2] = va.z; pu[3] = va.w;
    }
#pragma unroll
    for (int u = 0; u < 4; u++) {
        int idx = tid + u * 128;
        int r = idx >> 2, c4 = idx & 3;
        int rr = row0 + r;
        float4 v = *(const float4*)(feats + (size_t)rr * 16 + c4 * 4);  // rr < N0 always
        float* p = &sF[r * 17 + c4 * 4];
        p[0] = v.x; p[1] = v.y; p[2] = v.z; p[3] = v.w;
    }
#pragma unroll
    for (int u = 0; u < 8; u++)
        ((float4*)sW)[tid + u * 128] = ((const float4*)Ws1)[tid + u * 128];
    if (tid < 64) {
        sB[tid] = bs1[tid];
        sB[64 + tid] = bc1[tid];
        sB[128 + tid] = bc2[tid];
    }
    if (tid < 8) sB[192 + tid] = bc3[tid];
    __syncthreads();

    unsigned long long acc2[32];
#pragma unroll
    for (int j = 0; j < 32; j++) acc2[j] = pack2(sB[2 * j], sB[2 * j + 1]);
#pragma unroll 4
    for (int k = 0; k < 64; k++) {
        float a = sT[tid * 65 + k];
        fma64p(acc2, pack2(a, a), &sW[k * 64]);
    }
    __syncthreads();
#pragma unroll
    for (int u = 0; u < 8; u++)
        ((float4*)sW)[tid + u * 128] = ((const float4*)Wn1)[tid + u * 128];
    __syncthreads();
#pragma unroll 4
    for (int k = 0; k < 64; k++) {
        float a = sU[tid * 65 + k];
        fma64p(acc2, pack2(a, a), &sW[k * 64]);
    }

    // acc2 = h2 (no relu): write out
    if (valid) {
        float* out = h2out + (size_t)row * 64;
#pragma unroll
        for (int j4 = 0; j4 < 16; j4++) {
            float2 a = unpack2(acc2[2 * j4]);
            float2 b = unpack2(acc2[2 * j4 + 1]);
            *(float4*)&out[j4 * 4] = make_float4(a.x, a.y, b.x, b.y);
        }
    }
    __syncthreads();
    // park h2 in sU, stage Wc1 (80x64)
#pragma unroll
    for (int j = 0; j < 32; j++) {
        float2 p = unpack2(acc2[j]);
        sU[tid * 65 + 2 * j] = p.x;
        sU[tid * 65 + 2 * j + 1] = p.y;
    }
#pragma unroll
    for (int u = 0; u < 10; u++)
        ((float4*)sW)[tid + u * 128] = ((const float4*)Wc1)[tid + u * 128];
    __syncthreads();

    unsigned long long x2[32];
#pragma unroll
    for (int j = 0; j < 32; j++) x2[j] = pack2(sB[64 + 2 * j], sB[64 + 2 * j + 1]);
#pragma unroll 4
    for (int k = 0; k < 64; k++) {
        float a = sU[tid * 65 + k];
        fma64p(x2, pack2(a, a), &sW[k * 64]);
    }
#pragma unroll
    for (int k = 0; k < 16; k++) {
        float a = sF[tid * 17 + k];
        fma64p(x2, pack2(a, a), &sW[(64 + k) * 64]);
    }
    __syncthreads();
    // relu + park x in sT, stage Wc2
#pragma unroll
    for (int j = 0; j < 32; j++) {
        float2 p = unpack2(x2[j]);
        sT[tid * 65 + 2 * j]     = fmaxf(p.x, 0.f);
        sT[tid * 65 + 2 * j + 1] = fmaxf(p.y, 0.f);
    }
#pragma unroll
    for (int u = 0; u < 8; u++)
        ((float4*)sW)[tid + u * 128] = ((const float4*)Wc2)[tid + u * 128];
    __syncthreads();

#pragma unroll
    for (int j = 0; j < 32; j++) acc2[j] = pack2(sB[128 + 2 * j], sB[128 + 2 * j + 1]);
#pragma unroll 4
    for (int k = 0; k < 64; k++) {
        float a = sT[tid * 65 + k];
        fma64p(acc2, pack2(a, a), &sW[k * 64]);
    }
    __syncthreads();
    // relu + park x2 in sU, stage Wc3 (64x8)
#pragma unroll
    for (int j = 0; j < 32; j++) {
        float2 p = unpack2(acc2[j]);
        sU[tid * 65 + 2 * j]     = fmaxf(p.x, 0.f);
        sU[tid * 65 + 2 * j + 1] = fmaxf(p.y, 0.f);
    }
    if (tid < 128) ((float4*)sW)[tid] = ((const float4*)Wc3)[tid];
    __syncthreads();

    unsigned long long lg2[4];
#pragma unroll
    for (int j = 0; j < 4; j++) lg2[j] = pack2(sB[192 + 2 * j], sB[192 + 2 * j + 1]);
#pragma unroll 4
    for (int k = 0; k < 64; k++) {
        float a = sU[tid * 65 + k];
        unsigned long long aa = pack2(a, a);
        ulonglong2 w0 = *(const ulonglong2*)&sW[k * 8];
        ulonglong2 w1 = *(const ulonglong2*)&sW[k * 8 + 4];
        lg2[0] = fma2p(aa, w0.x, lg2[0]);
        lg2[1] = fma2p(aa, w0.y, lg2[1]);
        lg2[2] = fma2p(aa, w1.x, lg2[2]);
        lg2[3] = fma2p(aa, w1.y, lg2[3]);
    }
    if (valid) {
        float* lp = logits + (size_t)row * 8;
        float2 a = unpack2(lg2[0]), b = unpack2(lg2[1]);
        float2 c = unpack2(lg2[2]), d = unpack2(lg2[3]);
        *(float4*)(lp)     = make_float4(a.x, a.y, b.x, b.y);
        *(float4*)(lp + 4) = make_float4(c.x, c.y, d.x, d.y);
    }
}

// ---------------- host launch ----------------
extern "C" void kernel_launch(void* const* d_in, const int* in_sizes, int n_in,
                              void* d_out, int out_size) {
    const float* feats  = (const float*)d_in[0];
    const int*   ntypes = (const int*)d_in[1];
    const float* hemb   = (const float*)d_in[2];
    const int*   src0   = (const int*)d_in[3];
    const int*   dst0   = (const int*)d_in[4];
    const int*   src1   = (const int*)d_in[5];
    const int*   dst1   = (const int*)d_in[6];
    int wi = (n_in >= 31) ? 9 : 7;   // skip scalar n1, n2 if present
    const float* Wd  = (const float*)d_in[wi + 0];
    const float* bd  = (const float*)d_in[wi + 1];
    const float* Wi_ = (const float*)d_in[wi + 2];
    const float* bi  = (const float*)d_in[wi + 3];
    const float* Wn  = (const float*)d_in[wi + 4];
    const float* bn  = (const float*)d_in[wi + 5];
    const float* We1 = (const float*)d_in[wi + 6];
    const float* be1 = (const float*)d_in[wi + 7];
    const float* We2 = (const float*)d_in[wi + 8];
    const float* be2 = (const float*)d_in[wi + 9];
    const float* Ws0 = (const float*)d_in[wi + 10];
    const float* Wn0 = (const float*)d_in[wi + 11];
    const float* bs0 = (const float*)d_in[wi + 12];
    const float* Ws1 = (const float*)d_in[wi + 13];
    const float* Wn1 = (const float*)d_in[wi + 14];
    const float* bs1 = (const float*)d_in[wi + 15];
    const float* Wc1 = (const float*)d_in[wi + 16];
    const float* bc1 = (const float*)d_in[wi + 17];
    const float* Wc2 = (const float*)d_in[wi + 18];
    const float* bc2 = (const float*)d_in[wi + 19];
    const float* Wc3 = (const float*)d_in[wi + 20];
    const float* bc3 = (const float*)d_in[wi + 21];

    float* logits = (float*)d_out;
    float* h2out  = (float*)d_out + (size_t)N2C * 8;

    float *p_h, *p_agg0, *p_h1, *p_agg1;
    int *p_deg0, *p_off0, *p_cur0, *p_es0;
    int *p_deg1, *p_off1, *p_cur1, *p_es1;
    int *p_part0, *p_part1;
    cudaGetSymbolAddress((void**)&p_h,    g_h);
    cudaGetSymbolAddress((void**)&p_agg0, g_agg0);
    cudaGetSymbolAddress((void**)&p_h1,   g_h1);
    cudaGetSymbolAddress((void**)&p_agg1, g_agg1);
    cudaGetSymbolAddress((void**)&p_deg0, g_deg0);
    cudaGetSymbolAddress((void**)&p_off0, g_off0);
    cudaGetSymbolAddress((void**)&p_cur0, g_cur0);
    cudaGetSymbolAddress((void**)&p_es0,  g_es0);
    cudaGetSymbolAddress((void**)&p_deg1, g_deg1);
    cudaGetSymbolAddress((void**)&p_off1, g_off1);
    cudaGetSymbolAddress((void**)&p_cur1, g_cur1);
    cudaGetSymbolAddress((void**)&p_es1,  g_es1);
    cudaGetSymbolAddress((void**)&p_part0, g_part0);
    cudaGetSymbolAddress((void**)&p_part1, g_part1);

    const int SMEM_H1 = (128 * 65 + 64 * 64) * 4;              // 49664
    const int SMEM_H2 = (8320 + 8320 + 5120 + 2176 + 256) * 4; // 96768
    cudaFuncSetAttribute(k_h1,    cudaFuncAttributeMaxDynamicSharedMemorySize, SMEM_H1);
    cudaFuncSetAttribute(k_h2cls, cudaFuncAttributeMaxDynamicSharedMemorySize, SMEM_H2);

    int nb0 = (N1 + 1023) / 1024;   // 147
    int nb1 = (N2C + 1023) / 1024;  // 49
    int eb  = (E0C + E1C + 255) / 256;

    // ---- fused CSR build for both layers ----
    k_zero<<<(N1 + 255) / 256, 256>>>(p_deg0, p_deg1);
    k_hist2<<<eb, 256>>>(dst0, dst1, p_deg0, p_deg1);
    k_scan1<<<nb0 + nb1, 1024>>>(p_deg0, p_off0, p_part0, nb0, p_deg1, p_off1, p_part1);
    k_scan2<<<1, 1024>>>(p_part0, nb0, p_off0, p_part1, nb1, p_off1);
    k_scan3<<<nb0 + nb1, 1024>>>(p_off0, p_cur0, p_part0, nb0, p_off1, p_cur1, p_part1);
    k_scatter2<<<eb, 256>>>(src0, dst0, p_cur0, p_es0, src1, dst1, p_cur1, p_es1);

    // ---- feature build ----
    k_embed<<<(N0 + 255) / 256, 256>>>(hemb, We1, be1, We2, be2, p_h);
    k_proj<<<(N0 + 127) / 128, 128>>>(feats, ntypes, Wd, bd, Wi_, bi, Wn, bn, p_h);

    // ---- GNN layers + classifier ----
    k_agg<<<(N1 + 7) / 8, 256>>>(p_h, p_off0, p_es0, p_agg0, N1);
    k_h1<<<(N1 + 127) / 128, 128, SMEM_H1>>>(p_h, p_agg0, Ws0, Wn0, bs0, p_h1, N1);
    k_agg<<<(N2C + 7) / 8, 256>>>(p_h1, p_off1, p_es1, p_agg1, N2C);
    k_h2cls<<<(N2C + 127) / 128, 128, SMEM_H2>>>(p_h1, p_agg1, feats,
                                                 Ws1, Wn1, bs1,
                                                 Wc1, bc1, Wc2, bc2, Wc3, bc3,
                                                 logits, h2out);
}